// round 5
// baseline (speedup 1.0000x reference)
#include <cuda_runtime.h>
#include <math.h>
#include <stdint.h>

#define N_NODES 4096
#define F_IN    256
#define C_TOT   256
#define HEADS   4
#define F_OUT   64
#define JSPLIT  4
#define NWORDS  (N_NODES / 32)

__device__ float    g_h [N_NODES * C_TOT];
__device__ float    g_P1[N_NODES * HEADS];
__device__ float    g_P2[N_NODES * HEADS];
__device__ float    g_Q1[N_NODES * HEADS];
__device__ float    g_Q2[N_NODES * HEADS];
__device__ unsigned g_adjm[N_NODES * NWORDS];
__device__ float    g_part[JSPLIT * HEADS * N_NODES * F_OUT];  // partial numerators
__device__ float    g_pden[JSPLIT * HEADS * N_NODES];          // partial denominators

// ---------------------------------------------------------------------------
// K1: h = x @ W   (fp32 SIMT)
// ---------------------------------------------------------------------------
__global__ __launch_bounds__(256) void k_gemm(const float* __restrict__ x,
                                              const float* __restrict__ W) {
    __shared__ __align__(16) float As[16][64];
    __shared__ __align__(16) float Bs[16][64];
    const int t  = threadIdx.x;
    const int n0 = blockIdx.x * 64;
    const int m0 = blockIdx.y * 64;
    const int tx = t & 15, ty = t >> 4;

    float acc[4][4];
#pragma unroll
    for (int i = 0; i < 4; ++i)
#pragma unroll
        for (int j = 0; j < 4; ++j) acc[i][j] = 0.f;

    for (int k0 = 0; k0 < F_IN; k0 += 16) {
        {
            int row = t >> 2, k4 = (t & 3) * 4;
            float4 v = *(const float4*)&x[(m0 + row) * F_IN + k0 + k4];
            As[k4 + 0][row] = v.x; As[k4 + 1][row] = v.y;
            As[k4 + 2][row] = v.z; As[k4 + 3][row] = v.w;
        }
        {
            int krow = t >> 4, n4 = (t & 15) * 4;
            *(float4*)&Bs[krow][n4] = *(const float4*)&W[(k0 + krow) * C_TOT + n0 + n4];
        }
        __syncthreads();
#pragma unroll
        for (int kk = 0; kk < 16; ++kk) {
            float a[4], b[4];
            *(float4*)a = *(float4*)&As[kk][ty * 4];
            *(float4*)b = *(float4*)&Bs[kk][tx * 4];
#pragma unroll
            for (int i = 0; i < 4; ++i)
#pragma unroll
                for (int j = 0; j < 4; ++j) acc[i][j] += a[i] * b[j];
        }
        __syncthreads();
    }
#pragma unroll
    for (int i = 0; i < 4; ++i) {
        float4 v = make_float4(acc[i][0], acc[i][1], acc[i][2], acc[i][3]);
        *(float4*)&g_h[(m0 + ty * 4 + i) * C_TOT + n0 + tx * 4] = v;
    }
}

// ---------------------------------------------------------------------------
// K2: exp tables
// ---------------------------------------------------------------------------
__global__ __launch_bounds__(128) void k_prep(const float* __restrict__ a) {
    const int n    = blockIdx.x;
    const int h    = threadIdx.x >> 5;
    const int lane = threadIdx.x & 31;
    const float* base = g_h + n * C_TOT + h * F_OUT;

    float hv0 = base[lane], hv1 = base[lane + 32];
    float ei = hv0 * a[lane]      + hv1 * a[lane + 32];
    float ej = hv0 * a[64 + lane] + hv1 * a[96 + lane];
#pragma unroll
    for (int off = 16; off; off >>= 1) {
        ei += __shfl_down_sync(0xffffffffu, ei, off);
        ej += __shfl_down_sync(0xffffffffu, ej, off);
    }
    if (lane == 0) {
        int idx = n * HEADS + h;
        g_P1[idx] = expf(ei);
        g_P2[idx] = expf(0.2f * ei);
        g_Q1[idx] = expf(ej);
        g_Q2[idx] = expf(0.2f * ej);
    }
}

// ---------------------------------------------------------------------------
// K3a: pack adjacency to bitmask (64 MB -> 2 MB)
// ---------------------------------------------------------------------------
__global__ __launch_bounds__(128) void k_pack(const int* __restrict__ adj) {
    const int i    = blockIdx.x;
    const int w    = threadIdx.x >> 5;
    const int lane = threadIdx.x & 31;
    const int* row = adj + (size_t)i * N_NODES;
    for (int wd = w; wd < NWORDS; wd += 4) {
        int v = row[wd * 32 + lane];
        unsigned m = __ballot_sync(0xffffffffu, v != 0);
        if (lane == 0) g_adjm[i * NWORDS + wd] = m;
    }
}

// ---------------------------------------------------------------------------
// K3b: mma.sync tf32 aggregation, v3.
//  Warp = 32 i-rows (two m16 A tiles share every B fragment).
//  H tile stored f-permuted: hsP[j][(f&7)*8 + (f>>3)] so each thread's 8
//  B values (one per n-tile) are contiguous -> 2x LDS.128 per j-row.
// ---------------------------------------------------------------------------
__device__ __forceinline__ void mma_tf32(float c[4],
                                         unsigned a0, unsigned a1,
                                         unsigned a2, unsigned a3,
                                         unsigned b0, unsigned b1) {
    asm volatile(
        "mma.sync.aligned.m16n8k8.row.col.f32.tf32.tf32.f32 "
        "{%0,%1,%2,%3}, {%4,%5,%6,%7}, {%8,%9}, {%0,%1,%2,%3};"
        : "+f"(c[0]), "+f"(c[1]), "+f"(c[2]), "+f"(c[3])
        : "r"(a0), "r"(a1), "r"(a2), "r"(a3), "r"(b0), "r"(b1));
}
__device__ __forceinline__ unsigned to_tf32(float x) {
    unsigned u;
    asm("cvt.rna.tf32.f32 %0, %1;" : "=r"(u) : "f"(x));
    return u;
}

#define HSTR 72
#define JTILE 64
#define JPER  (N_NODES / JSPLIT)   // 1024 j per CTA

__global__ __launch_bounds__(128) void k_aggr_v3() {
    __shared__ __align__(16) float  hsP[JTILE * HSTR];   // 18 KB
    __shared__ __align__(8)  float2 qs[JTILE];

    const int t    = threadIdx.x;
    const int w    = t >> 5;
    const int lane = t & 31;
    const int g    = lane >> 2;
    const int tg   = lane & 3;
    const int head = blockIdx.y;
    const int js   = blockIdx.z;
    const int i0   = blockIdx.x * 128 + w * 32;   // warp's first row

    // four A rows per thread: g, g+8 (tile0) ; g+16, g+24 (tile1)
    int rows[4];
    float p1[4], p2[4];
#pragma unroll
    for (int r = 0; r < 4; ++r) {
        rows[r] = i0 + g + r * 8;
        p1[r] = g_P1[rows[r] * HEADS + head];
        p2[r] = g_P2[rows[r] * HEADS + head];
    }

    float acc0[8][4], acc1[8][4];
#pragma unroll
    for (int nt = 0; nt < 8; ++nt)
#pragma unroll
        for (int k = 0; k < 4; ++k) { acc0[nt][k] = 0.f; acc1[nt][k] = 0.f; }
    float den[4] = {0.f, 0.f, 0.f, 0.f};

    for (int tile = 0; tile < JPER / JTILE; ++tile) {
        const int j0 = js * JPER + tile * JTILE;

        __syncthreads();
        // ---- stage H tile, f-permuted, tf32-rounded ----
#pragma unroll
        for (int r = 0; r < 8; ++r) {
            int idx = t + r * 128;              // 1024 float4 slots
            int jj = idx >> 4, u = idx & 15;
            float4 v = *(const float4*)&g_h[(size_t)(j0 + jj) * C_TOT + head * F_OUT + u * 4];
            float* row = &hsP[jj * HSTR];
            int f0 = u * 4;
#pragma unroll
            for (int c = 0; c < 4; ++c) {
                int f = f0 + c;
                float vc = (c == 0) ? v.x : (c == 1) ? v.y : (c == 2) ? v.z : v.w;
                row[(f & 7) * 8 + (f >> 3)] = __uint_as_float(to_tf32(vc));
            }
        }
        if (t < JTILE)
            qs[t] = make_float2(g_Q1[(j0 + t) * HEADS + head],
                                g_Q2[(j0 + t) * HEADS + head]);
        __syncthreads();

        // adjacency words for this 64-j window (2 words x 4 rows)
        unsigned mw[4][2];
        const int wd = j0 >> 5;
#pragma unroll
        for (int r = 0; r < 4; ++r) {
            mw[r][0] = g_adjm[rows[r] * NWORDS + wd];
            mw[r][1] = g_adjm[rows[r] * NWORDS + wd + 1];
        }

#pragma unroll
        for (int kk = 0; kk < 8; ++kk) {
            const int j_lo = kk * 8 + tg;
            const int j_hi = j_lo + 4;
            const int sh   = (kk & 3) * 8;
            const int wsel = kk >> 2;

            const float2 qlo = qs[j_lo];
            const float2 qhi = qs[j_hi];

            float bl[8], bh[8];
            *(float4*)&bl[0] = *(const float4*)&hsP[j_lo * HSTR + g * 8];
            *(float4*)&bl[4] = *(const float4*)&hsP[j_lo * HSTR + g * 8 + 4];
            *(float4*)&bh[0] = *(const float4*)&hsP[j_hi * HSTR + g * 8];
            *(float4*)&bh[4] = *(const float4*)&hsP[j_hi * HSTR + g * 8 + 4];

            unsigned ulo[4], uhi[4];
#pragma unroll
            for (int r = 0; r < 4; ++r) {
                float vlo = fmaxf(p1[r] * qlo.x, p2[r] * qlo.y);
                float vhi = fmaxf(p1[r] * qhi.x, p2[r] * qhi.y);
                vlo = ((mw[r][wsel] >> (sh + tg))     & 1u) ? vlo : 0.f;
                vhi = ((mw[r][wsel] >> (sh + tg + 4)) & 1u) ? vhi : 0.f;
                ulo[r] = to_tf32(vlo);
                uhi[r] = to_tf32(vhi);
                den[r] += __uint_as_float(ulo[r]) + __uint_as_float(uhi[r]);
            }
#pragma unroll
            for (int nt = 0; nt < 8; ++nt) {
                unsigned b0 = __float_as_uint(bl[nt]);
                unsigned b1 = __float_as_uint(bh[nt]);
                mma_tf32(acc0[nt], ulo[0], ulo[1], uhi[0], uhi[1], b0, b1);
                mma_tf32(acc1[nt], ulo[2], ulo[3], uhi[2], uhi[3], b0, b1);
            }
        }
    }

    // ---- epilogue: quad-reduce denominators, write partials ----
#pragma unroll
    for (int r = 0; r < 4; ++r) {
        den[r] += __shfl_xor_sync(0xffffffffu, den[r], 1);
        den[r] += __shfl_xor_sync(0xffffffffu, den[r], 2);
    }
    const size_t pb = (size_t)(js * HEADS + head) * N_NODES;
    if (tg == 0) {
#pragma unroll
        for (int r = 0; r < 4; ++r) g_pden[pb + rows[r]] = den[r];
    }
    // D fragment: acc[nt][0,1] -> row g (+base), cols nt*8 + tg*2, +1
    //             acc[nt][2,3] -> row g+8
    float* p0 = &g_part[(pb + rows[0]) * F_OUT];
    float* p1o = &g_part[(pb + rows[1]) * F_OUT];
    float* p2o = &g_part[(pb + rows[2]) * F_OUT];
    float* p3o = &g_part[(pb + rows[3]) * F_OUT];
#pragma unroll
    for (int nt = 0; nt < 8; ++nt) {
        const int f = nt * 8 + tg * 2;
        *(float2*)&p0[f]  = make_float2(acc0[nt][0], acc0[nt][1]);
        *(float2*)&p1o[f] = make_float2(acc0[nt][2], acc0[nt][3]);
        *(float2*)&p2o[f] = make_float2(acc1[nt][0], acc1[nt][1]);
        *(float2*)&p3o[f] = make_float2(acc1[nt][2], acc1[nt][3]);
    }
}

// ---------------------------------------------------------------------------
// K4: combine partials over j-splits and heads
// ---------------------------------------------------------------------------
__global__ __launch_bounds__(256) void k_combine(float* __restrict__ out) {
    const int t = blockIdx.x * 256 + threadIdx.x;
    const int i = t >> 6;
    const int f = t & 63;
    float v = 0.f;
#pragma unroll
    for (int h = 0; h < HEADS; ++h) {
        float num = 0.f, den = 0.f;
#pragma unroll
        for (int s = 0; s < JSPLIT; ++s) {
            num += g_part[((size_t)(s * HEADS + h) * N_NODES + i) * F_OUT + f];
            den += g_pden[(size_t)(s * HEADS + h) * N_NODES + i];
        }
        v += num / den;
    }
    out[t] = 0.25f * v;
}

// ---------------------------------------------------------------------------
extern "C" void kernel_launch(void* const* d_in, const int* in_sizes, int n_in,
                              void* d_out, int out_size) {
    const float* x   = (const float*)d_in[0];
    const int*   adj = (const int*)  d_in[1];
    const float* W   = (const float*)d_in[2];
    const float* a   = (const float*)d_in[3];
    float* out = (float*)d_out;

    k_gemm<<<dim3(C_TOT / 64, N_NODES / 64), 256>>>(x, W);
    k_prep<<<N_NODES, 128>>>(a);
    k_pack<<<N_NODES, 128>>>(adj);
    k_aggr_v3<<<dim3(N_NODES / 128, HEADS, JSPLIT), 128>>>();
    k_combine<<<(N_NODES * F_OUT) / 256, 256>>>(out);
}